// round 1
// baseline (speedup 1.0000x reference)
#include <cuda_runtime.h>

// out[i,j,:] = (i==j) ? 0 : A[min(i,j)] + B[max(i,j)] + b
// where A = x @ W[:, :256].T, B = x @ W[:, 256:].T
//
// Stage 1: C[512,512] = x[512,256] @ Wt[256,512] + 0.5*b  (Wt col o<256 -> W[o][k], o>=256 -> W[o-256][k+256])
// Stage 2: broadcast-add expansion, symmetric tiles written twice.

__device__ float g_C[512 * 512];   // 1 MB scratch (fits L2)

__global__ __launch_bounds__(256, 1)
void gemm_kernel(const float* __restrict__ x,
                 const float* __restrict__ W,
                 const float* __restrict__ bias) {
    __shared__ float sA[16][64];   // [k][m]
    __shared__ float sB[16][64];   // [k][o]

    const int tid = threadIdx.x;
    const int tx = tid & 15;       // col group
    const int ty = tid >> 4;       // row group
    const int bx = blockIdx.x;     // N tile (o)
    const int by = blockIdx.y;     // M tile (i)

    // loader mapping: each thread loads one float4 per tile per k-chunk
    const int lrow = tid >> 2;     // 0..63
    const int lkq  = tid & 3;      // 0..3 (which float4 of the 16-wide k chunk)

    const int o = bx * 64 + lrow;
    const long wbase = (o < 256) ? (long)o * 512 : (long)(o - 256) * 512 + 256;
    const long xbase = (long)(by * 64 + lrow) * 256;

    float acc[4][4];
#pragma unroll
    for (int m = 0; m < 4; m++)
#pragma unroll
        for (int n = 0; n < 4; n++) acc[m][n] = 0.0f;

    for (int k0 = 0; k0 < 256; k0 += 16) {
        float4 va = *(const float4*)&x[xbase + k0 + lkq * 4];
        float4 vb = *(const float4*)&W[wbase + k0 + lkq * 4];
        __syncthreads();           // protect previous iteration's reads
        sA[lkq * 4 + 0][lrow] = va.x;
        sA[lkq * 4 + 1][lrow] = va.y;
        sA[lkq * 4 + 2][lrow] = va.z;
        sA[lkq * 4 + 3][lrow] = va.w;
        sB[lkq * 4 + 0][lrow] = vb.x;
        sB[lkq * 4 + 1][lrow] = vb.y;
        sB[lkq * 4 + 2][lrow] = vb.z;
        sB[lkq * 4 + 3][lrow] = vb.w;
        __syncthreads();

#pragma unroll
        for (int kk = 0; kk < 16; kk++) {
            float4 a4 = *(const float4*)&sA[kk][ty * 4];
            float4 b4 = *(const float4*)&sB[kk][tx * 4];
            float am[4] = {a4.x, a4.y, a4.z, a4.w};
            float bn[4] = {b4.x, b4.y, b4.z, b4.w};
#pragma unroll
            for (int m = 0; m < 4; m++)
#pragma unroll
                for (int n = 0; n < 4; n++)
                    acc[m][n] = fmaf(am[m], bn[n], acc[m][n]);
        }
    }

    // epilogue: fold 0.5*b (full b re-assembles in the expansion sum)
    float bb[4];
#pragma unroll
    for (int n = 0; n < 4; n++)
        bb[n] = 0.5f * bias[(bx * 64 + tx * 4 + n) & 255];

#pragma unroll
    for (int m = 0; m < 4; m++) {
        int row = by * 64 + ty * 4 + m;
        float4 v = make_float4(acc[m][0] + bb[0], acc[m][1] + bb[1],
                               acc[m][2] + bb[2], acc[m][3] + bb[3]);
        *(float4*)&g_C[(long)row * 512 + bx * 64 + tx * 4] = v;
    }
}

__global__ __launch_bounds__(256, 1)
void expand_kernel(float4* __restrict__ out) {
    const int tj = blockIdx.x;     // 0..31
    const int ti = blockIdx.y;     // 0..31
    if (ti > tj) return;           // only upper-triangular tiles do work

    __shared__ float4 sAs[16][64];  // A rows for i-tile   (16 KB)
    __shared__ float4 sBs[16][64];  // B rows for j-tile   (16 KB)

    const int tid = threadIdx.x;
    const float4* C4 = (const float4*)g_C;   // each C row = 128 float4 (A half: 0..63, B half: 64..127)

#pragma unroll
    for (int idx = tid; idx < 16 * 64; idx += 256) {
        int r = idx >> 6, c = idx & 63;
        sAs[r][c] = C4[(long)(ti * 16 + r) * 128 + c];
        sBs[r][c] = C4[(long)(tj * 16 + r) * 128 + 64 + c];
    }
    __syncthreads();

    const int o4 = tid & 63;       // which float4 of the 256-float feature row
    const int g  = tid >> 6;       // 0..3

    if (ti == tj) {
        // diagonal tile: each (ii,jj) pair writes exactly its own cell
#pragma unroll 4
        for (int p = g; p < 256; p += 4) {
            int ii = p >> 4, jj = p & 15;
            int i = ti * 16 + ii, j = tj * 16 + jj;
            float4 v;
            if (ii == jj) {
                v = make_float4(0.f, 0.f, 0.f, 0.f);
            } else {
                int lo = min(ii, jj), hi = max(ii, jj);
                float4 a = sAs[lo][o4];
                float4 b = sBs[hi][o4];
                v = make_float4(a.x + b.x, a.y + b.y, a.z + b.z, a.w + b.w);
            }
            out[((long)i * 512 + j) * 64 + o4] = v;
        }
    } else {
        // strictly-upper tile: i < j always; write (i,j) and its mirror (j,i)
#pragma unroll 4
        for (int p = g; p < 256; p += 4) {
            int ii = p >> 4, jj = p & 15;
            int i = ti * 16 + ii, j = tj * 16 + jj;
            float4 a = sAs[ii][o4];
            float4 b = sBs[jj][o4];
            float4 v = make_float4(a.x + b.x, a.y + b.y, a.z + b.z, a.w + b.w);
            out[((long)i * 512 + j) * 64 + o4] = v;
            out[((long)j * 512 + i) * 64 + o4] = v;
        }
    }
}

extern "C" void kernel_launch(void* const* d_in, const int* in_sizes, int n_in,
                              void* d_out, int out_size) {
    const float* x = (const float*)d_in[0];   // [512, 256]
    const float* W = (const float*)d_in[1];   // [256, 512]
    const float* b = (const float*)d_in[2];   // [256]

    gemm_kernel<<<dim3(8, 8), 256>>>(x, W, b);
    expand_kernel<<<dim3(32, 32), 256>>>((float4*)d_out);
}

// round 2
// speedup vs baseline: 1.1785x; 1.1785x over previous
#include <cuda_runtime.h>

// out[i,j,:] = (i==j) ? 0 : A[min(i,j)] + B[max(i,j)] + b
// where A = x @ W[:, :256].T, B = x @ W[:, 256:].T
//
// Stage 1: C[512,512] = x[512,256] @ Wt[256,512] + 0.5*b
//          (Wt col o<256 -> W[o][k], o>=256 -> W[o-256][k+256])
// Stage 2: broadcast-add expansion over the 528 upper-triangular 16x16 tiles,
//          each writing itself and its mirror.

__device__ float g_C[512 * 512];   // 1 MB scratch (fits L2)

// 128 blocks (8 n-tiles x 16 m-tiles), tile 32M x 64N, 256 threads, 2x4 microtile.
__global__ __launch_bounds__(256, 1)
void gemm_kernel(const float* __restrict__ x,
                 const float* __restrict__ W,
                 const float* __restrict__ bias) {
    __shared__ float sA[16][32];   // [k][m]
    __shared__ float sB[16][64];   // [k][o]

    const int tid = threadIdx.x;
    const int tx = tid & 15;       // n group (4 cols each)
    const int ty = tid >> 4;       // m group (2 rows each), 0..15
    const int bx = blockIdx.x;     // N tile (64 wide)
    const int by = blockIdx.y;     // M tile (32 tall)

    // loaders
    const int lrow = tid >> 2;     // A: 0..31 (tid<128), B: 0..63
    const int lkq  = tid & 3;      // which float4 of the 16-wide k chunk

    const int o = bx * 64 + lrow;
    const long wbase = (o < 256) ? (long)o * 512 : (long)(o - 256) * 512 + 256;
    const long xbase = (long)(by * 32 + lrow) * 256;   // valid only for tid<128

    float acc[2][4];
#pragma unroll
    for (int m = 0; m < 2; m++)
#pragma unroll
        for (int n = 0; n < 4; n++) acc[m][n] = 0.0f;

    for (int k0 = 0; k0 < 256; k0 += 16) {
        float4 va = make_float4(0.f, 0.f, 0.f, 0.f);
        if (tid < 128) va = *(const float4*)&x[xbase + k0 + lkq * 4];
        float4 vb = *(const float4*)&W[wbase + k0 + lkq * 4];
        __syncthreads();           // protect previous iteration's reads
        if (tid < 128) {
            sA[lkq * 4 + 0][lrow] = va.x;
            sA[lkq * 4 + 1][lrow] = va.y;
            sA[lkq * 4 + 2][lrow] = va.z;
            sA[lkq * 4 + 3][lrow] = va.w;
        }
        sB[lkq * 4 + 0][lrow] = vb.x;
        sB[lkq * 4 + 1][lrow] = vb.y;
        sB[lkq * 4 + 2][lrow] = vb.z;
        sB[lkq * 4 + 3][lrow] = vb.w;
        __syncthreads();

#pragma unroll
        for (int kk = 0; kk < 16; kk++) {
            float2 a2 = *(const float2*)&sA[kk][ty * 2];
            float4 b4 = *(const float4*)&sB[kk][tx * 4];
            float am[2] = {a2.x, a2.y};
            float bn[4] = {b4.x, b4.y, b4.z, b4.w};
#pragma unroll
            for (int m = 0; m < 2; m++)
#pragma unroll
                for (int n = 0; n < 4; n++)
                    acc[m][n] = fmaf(am[m], bn[n], acc[m][n]);
        }
    }

    // epilogue: fold 0.5*b (full b re-assembles in the expansion sum)
    float bb[4];
#pragma unroll
    for (int n = 0; n < 4; n++)
        bb[n] = 0.5f * bias[(bx * 64 + tx * 4 + n) & 255];

#pragma unroll
    for (int m = 0; m < 2; m++) {
        int row = by * 32 + ty * 2 + m;
        float4 v = make_float4(acc[m][0] + bb[0], acc[m][1] + bb[1],
                               acc[m][2] + bb[2], acc[m][3] + bb[3]);
        *(float4*)&g_C[(long)row * 512 + bx * 64 + tx * 4] = v;
    }
}

// 528 blocks = exactly the upper-triangular 16x16 cell tiles (ti <= tj).
__global__ __launch_bounds__(256, 1)
void expand_kernel(float4* __restrict__ out) {
    // decode linear block id -> (ti, tj), ti <= tj, row ti has (32 - ti) tiles
    int rem = blockIdx.x;
    int ti = 0;
#pragma unroll 1
    while (rem >= 32 - ti) { rem -= 32 - ti; ti++; }
    const int tj = ti + rem;

    __shared__ float4 sAs[16][64];  // A rows for i-tile   (16 KB)
    __shared__ float4 sBs[16][64];  // B rows for j-tile   (16 KB)

    const int tid = threadIdx.x;
    const float4* C4 = (const float4*)g_C;   // row = 128 float4 (A: 0..63, B: 64..127)

#pragma unroll
    for (int idx = tid; idx < 16 * 64; idx += 256) {
        int r = idx >> 6, c = idx & 63;
        sAs[r][c] = C4[(long)(ti * 16 + r) * 128 + c];
        sBs[r][c] = C4[(long)(tj * 16 + r) * 128 + 64 + c];
    }
    __syncthreads();

    const int o4 = tid & 63;       // which float4 of the 256-float feature row
    const int g  = tid >> 6;       // 0..3

    if (ti == tj) {
        // diagonal tile: each (ii,jj) pair writes exactly its own cell
#pragma unroll 4
        for (int p = g; p < 256; p += 4) {
            int ii = p >> 4, jj = p & 15;
            int i = ti * 16 + ii, j = tj * 16 + jj;
            float4 v;
            if (ii == jj) {
                v = make_float4(0.f, 0.f, 0.f, 0.f);
            } else {
                int lo = min(ii, jj), hi = max(ii, jj);
                float4 a = sAs[lo][o4];
                float4 b = sBs[hi][o4];
                v = make_float4(a.x + b.x, a.y + b.y, a.z + b.z, a.w + b.w);
            }
            __stcs(&out[((long)i * 512 + j) * 64 + o4], v);
        }
    } else {
        // strictly-upper tile: i < j always; write (i,j) and its mirror (j,i)
#pragma unroll 4
        for (int p = g; p < 256; p += 4) {
            int ii = p >> 4, jj = p & 15;
            int i = ti * 16 + ii, j = tj * 16 + jj;
            float4 a = sAs[ii][o4];
            float4 b = sBs[jj][o4];
            float4 v = make_float4(a.x + b.x, a.y + b.y, a.z + b.z, a.w + b.w);
            __stcs(&out[((long)i * 512 + j) * 64 + o4], v);
            __stcs(&out[((long)j * 512 + i) * 64 + o4], v);
        }
    }
}

extern "C" void kernel_launch(void* const* d_in, const int* in_sizes, int n_in,
                              void* d_out, int out_size) {
    const float* x = (const float*)d_in[0];   // [512, 256]
    const float* W = (const float*)d_in[1];   // [256, 512]
    const float* b = (const float*)d_in[2];   // [256]

    gemm_kernel<<<dim3(8, 16), 256>>>(x, W, b);
    expand_kernel<<<528, 256>>>((float4*)d_out);
}